// round 1
// baseline (speedup 1.0000x reference)
#include <cuda_runtime.h>

#define BB 1024
#define TT 128
#define KK 128
#define START_TAG 126
#define STOP_TAG 127
#define CAP 31

// Scratch (static __device__ arrays; allocation is forbidden)
__device__ float         g_part [(size_t)BB * TT * KK];   // 64 MB partition history
__device__ float         g_cvals[(size_t)BB * TT * 32];   // 16 MB candidate partition values
__device__ unsigned char g_cidx [(size_t)BB * TT * 32];   //  4 MB candidate prev indices
__device__ unsigned char g_ccnt [(size_t)BB * TT];        // candidate counts

// Per-warp length from the monotone mask row. Mask dtype detected from first word:
// bool -> 0x01010101 (first 4 entries always true, len>=64), float32 -> 0x3F800000, else int32.
__device__ __forceinline__ int warp_len(const void* masks, int b, int lane) {
    unsigned w0 = *(const unsigned*)masks;
    int cnt;
    if (w0 == 0x01010101u) {
        unsigned v = ((const unsigned*)((const char*)masks + (size_t)b * TT))[lane];
        cnt = __popc(v & 0x01010101u);
    } else if (w0 == 0x3F800000u) {
        float4 v = ((const float4*)((const float*)masks + (size_t)b * TT))[lane];
        cnt = (v.x != 0.0f) + (v.y != 0.0f) + (v.z != 0.0f) + (v.w != 0.0f);
    } else {
        int4 v = ((const int4*)((const int*)masks + (size_t)b * TT))[lane];
        cnt = (v.x != 0) + (v.y != 0) + (v.z != 0) + (v.w != 0);
    }
    return __reduce_add_sync(0xffffffffu, cnt);
}

// ---------------------------------------------------------------------------
// Forward: warp per batch. Pruned max-plus recurrence; stores partition history
// and per-step candidate lists for the backward pass.
// ---------------------------------------------------------------------------
extern "C" __global__ void __launch_bounds__(256)
fwd_kernel(const float* __restrict__ feats,
           const float* __restrict__ trans,
           const void*  __restrict__ masks) {
    extern __shared__ float ts[];            // [prev*128 + cur], 64 KB
    __shared__ float s_wr[4];
    __shared__ float s_delta;

    int tid = threadIdx.x;

    // Load transitions into smem (coalesced float4)
    for (int i = tid; i < KK * KK / 4; i += 256)
        ((float4*)ts)[i] = ((const float4*)trans)[i];
    __syncthreads();

    // Exact prune bound: Delta = max over cur of (max-min of trans[:,cur]) + FP margin
    if (tid < 128) {
        float mx = -3.4e38f, mn = 3.4e38f;
        #pragma unroll 8
        for (int p = 0; p < 128; p++) {
            float v = ts[p * 128 + tid];
            mx = fmaxf(mx, v); mn = fminf(mn, v);
        }
        float r = mx - mn;
        #pragma unroll
        for (int o = 16; o; o >>= 1) r = fmaxf(r, __shfl_xor_sync(0xffffffffu, r, o));
        if ((tid & 31) == 0) s_wr[tid >> 5] = r;
    }
    __syncthreads();
    if (tid == 0)
        s_delta = fmaxf(fmaxf(s_wr[0], s_wr[1]), fmaxf(s_wr[2], s_wr[3])) + 1e-3f;
    __syncthreads();
    float delta = s_delta;

    int w = tid >> 5, lane = tid & 31;
    int b = blockIdx.x * 8 + w;
    int last = warp_len(masks, b, lane) - 1;

    const float*   fb = feats   + (size_t)b * TT * KK;
    float*         ph = g_part  + (size_t)b * TT * KK;
    float*         cv = g_cvals + (size_t)b * TT * 32;
    unsigned char* cx = g_cidx  + (size_t)b * TT * 32;
    unsigned char* cc = g_ccnt  + (size_t)b * TT;

    int c0 = lane * 4;           // this lane owns cur = c0..c0+3, prev = c0..c0+3

    // t = 0: partition = feats[:,0,:] + trans[START,:]
    float4 f0  = *(const float4*)(fb + c0);
    float4 tr0 = *(const float4*)(ts + START_TAG * 128 + c0);
    float v0 = f0.x + tr0.x, v1 = f0.y + tr0.y, v2 = f0.z + tr0.z, v3 = f0.w + tr0.w;
    *(float4*)(ph + c0) = make_float4(v0, v1, v2, v3);

    float4 fn = *(const float4*)(fb + KK + c0);   // prefetch feat row t=1 (len>=64)

    for (int t = 1; t <= last; t++) {
        float4 fc = fn;
        if (t < last) fn = *(const float4*)(fb + (t + 1) * KK + c0);

        // warp max of partition
        float m = fmaxf(fmaxf(v0, v1), fmaxf(v2, v3));
        #pragma unroll
        for (int o = 16; o; o >>= 1) m = fmaxf(m, __shfl_xor_sync(0xffffffffu, m, o));
        float thr = m - delta;

        unsigned b0 = __ballot_sync(0xffffffffu, v0 >= thr);
        unsigned b1 = __ballot_sync(0xffffffffu, v1 >= thr);
        unsigned b2 = __ballot_sync(0xffffffffu, v2 >= thr);
        unsigned b3 = __ballot_sync(0xffffffffu, v3 >= thr);
        int n0 = __popc(b0), n1 = __popc(b1), n2 = __popc(b2);
        int ncand = n0 + n1 + n2 + __popc(b3);

        // store candidate records for backward (prev index + partition value)
        if (ncand <= CAP) {
            unsigned lm = (1u << lane) - 1u;
            if ((b0 >> lane) & 1u) { int p =              __popc(b0 & lm); cv[t*32+p] = v0; cx[t*32+p] = (unsigned char)(c0 + 0); }
            if ((b1 >> lane) & 1u) { int p = n0 +         __popc(b1 & lm); cv[t*32+p] = v1; cx[t*32+p] = (unsigned char)(c0 + 1); }
            if ((b2 >> lane) & 1u) { int p = n0+n1 +      __popc(b2 & lm); cv[t*32+p] = v2; cx[t*32+p] = (unsigned char)(c0 + 2); }
            if ((b3 >> lane) & 1u) { int p = n0+n1+n2 +   __popc(b3 & lm); cv[t*32+p] = v3; cx[t*32+p] = (unsigned char)(c0 + 3); }
        }
        if (lane == 0) cc[t] = (unsigned char)min(ncand, 255);

        // new_part[cur] = max over candidate prev of (part[prev] + trans[prev][cur])
        float best0 = -3.4e38f, best1 = -3.4e38f, best2 = -3.4e38f, best3 = -3.4e38f;
        #define PROC(BM, VV, COMP)                                                        \
        {   unsigned mm = (BM);                                                           \
            while (mm) {                                                                  \
                int l = __ffs(mm) - 1; mm &= mm - 1;                                      \
                float pv = __shfl_sync(0xffffffffu, (VV), l);                             \
                float4 tr4 = *(const float4*)(ts + (l * 4 + (COMP)) * 128 + c0);          \
                best0 = fmaxf(best0, pv + tr4.x); best1 = fmaxf(best1, pv + tr4.y);       \
                best2 = fmaxf(best2, pv + tr4.z); best3 = fmaxf(best3, pv + tr4.w);       \
            }                                                                             \
        }
        PROC(b0, v0, 0)
        PROC(b1, v1, 1)
        PROC(b2, v2, 2)
        PROC(b3, v3, 3)
        #undef PROC

        v0 = best0 + fc.x; v1 = best1 + fc.y; v2 = best2 + fc.z; v3 = best3 + fc.w;
        *(float4*)(ph + t * KK + c0) = make_float4(v0, v1, v2, v3);
    }
}

// ---------------------------------------------------------------------------
// Backward: warp per batch (all lanes redundant -> no reductions on the chain).
// STOP argmax over all prev (first-index ties), then backtrack via candidate
// lists; fallback full scan if a step overflowed the candidate cap.
// ---------------------------------------------------------------------------
extern "C" __global__ void __launch_bounds__(256)
bwd_kernel(const float* __restrict__ feats,
           const float* __restrict__ trans,
           const void*  __restrict__ masks,
           float* __restrict__ out_score,
           float* __restrict__ out_dec) {
    extern __shared__ float tt[];            // transposed: [cur*129 + prev], 66048 B
    int tid = threadIdx.x;
    for (int i = tid; i < KK * KK; i += 256) {
        int prev = i >> 7, cur = i & 127;
        tt[cur * 129 + prev] = trans[i];     // coalesced LDG, conflict-free STS (129 stride)
    }
    __syncthreads();

    int w = tid >> 5, lane = tid & 31;
    int b = blockIdx.x * 8 + w;
    int last = warp_len(masks, b, lane) - 1;

    const float*         ph  = g_part  + (size_t)b * TT * KK;
    const float*         fb  = feats   + (size_t)b * TT * KK;
    const float*         cvp = g_cvals + (size_t)b * TT * 32;
    const unsigned char* cxp = g_cidx  + (size_t)b * TT * 32;
    const unsigned char* ccp = g_ccnt  + (size_t)b * TT;

    int c0 = lane * 4;

    // pointer / path_score: argmax_prev (part_last[prev] + trans[prev][STOP]), first index on tie
    float4 p = *(const float4*)(ph + (size_t)last * KK + c0);
    float q0 = p.x + tt[STOP_TAG * 129 + c0 + 0];
    float q1 = p.y + tt[STOP_TAG * 129 + c0 + 1];
    float q2 = p.z + tt[STOP_TAG * 129 + c0 + 2];
    float q3 = p.w + tt[STOP_TAG * 129 + c0 + 3];
    float bestv = q0; int besti = c0;
    if (q1 > bestv) { bestv = q1; besti = c0 + 1; }
    if (q2 > bestv) { bestv = q2; besti = c0 + 2; }
    if (q3 > bestv) { bestv = q3; besti = c0 + 3; }
    #pragma unroll
    for (int o = 16; o; o >>= 1) {
        float ov = __shfl_xor_sync(0xffffffffu, bestv, o);
        int   oi = __shfl_xor_sync(0xffffffffu, besti, o);
        if (ov > bestv || (ov == bestv && oi < besti)) { bestv = ov; besti = oi; }
    }
    int cur = besti;

    float* od = out_dec ? out_dec + (size_t)b * TT : nullptr;
    if (out_score && lane == 0) out_score[b] = bestv;
    if (od) {
        for (int t = last + 1 + lane; t < TT - 1; t += 32) od[t] = 0.0f;   // masked tail -> 0
        if (lane == 0) { od[TT - 1] = (float)cur; od[last] = (float)cur; } // reference quirk
    }

    // backtrack t = last .. 1 ; all lanes compute identically (cur is uniform)
    float4 fr  = *(const float4*)(fb + (size_t)last * KK + c0);   // feat row t
    float4 frn = fr;
    for (int t = last; t >= 1; t--) {
        if (t > 1) {
            frn = *(const float4*)(fb + (size_t)(t - 1) * KK + c0);
            asm volatile("prefetch.global.L1 [%0];" :: "l"(cvp + (size_t)(t - 1) * 32));
            asm volatile("prefetch.global.L1 [%0];" :: "l"(cxp + (size_t)(t - 1) * 32));
        }
        // feat[b][t][cur]: select component + shfl from the register row (cur uniform)
        float fsel = (cur & 2) ? ((cur & 1) ? fr.w : fr.z) : ((cur & 1) ? fr.y : fr.x);
        float fcur = __shfl_sync(0xffffffffu, fsel, cur >> 2);

        int cnt = ccp[t];
        float bv = -3.4e38f; int bi = 0;
        if (cnt <= CAP) {
            for (int j = 0; j < cnt; j++) {
                float pv = __ldg(cvp + t * 32 + j);
                int   ci = cxp[t * 32 + j];
                float q  = (pv + tt[cur * 129 + ci]) + fcur;   // matches ref association
                if (q > bv || (q == bv && ci < bi)) { bv = q; bi = ci; }
            }
        } else {   // rare overflow: exact full scan, ascending -> first-index ties
            const float* prow = ph + (size_t)(t - 1) * KK;
            for (int pi = 0; pi < 128; pi++) {
                float q = (__ldg(prow + pi) + tt[cur * 129 + pi]) + fcur;
                if (q > bv) { bv = q; bi = pi; }
            }
        }
        cur = bi;
        if (od && lane == 0) od[t - 1] = (float)cur;
        fr = frn;
    }
}

// ---------------------------------------------------------------------------
extern "C" void kernel_launch(void* const* d_in, const int* in_sizes, int n_in,
                              void* d_out, int out_size) {
    const float* feats = nullptr;
    const float* trans = nullptr;
    const void*  masks = nullptr;
    for (int i = 0; i < n_in; i++) {
        if      (in_sizes[i] == BB * TT * KK) feats = (const float*)d_in[i];
        else if (in_sizes[i] == KK * KK)      trans = (const float*)d_in[i];
        else if (in_sizes[i] == BB * TT)      masks = d_in[i];
    }
    if (!feats || !trans || !masks) return;

    float* out   = (float*)d_out;
    float* score = nullptr;
    float* dec   = nullptr;
    if (out_size == BB * TT + BB) { score = out; dec = out + BB; }   // (path_score, decode)
    else if (out_size == BB * TT) { dec = out; }
    else if (out_size == BB)      { score = out; }
    else                          { score = out; if (out_size >= BB * TT + BB) dec = out + BB; }

    cudaFuncSetAttribute(fwd_kernel, cudaFuncAttributeMaxDynamicSharedMemorySize, 65536);
    cudaFuncSetAttribute(bwd_kernel, cudaFuncAttributeMaxDynamicSharedMemorySize, 66048);

    fwd_kernel<<<BB / 8, 256, 65536>>>(feats, trans, masks);
    bwd_kernel<<<BB / 8, 256, 66048>>>(feats, trans, masks, score, dec);
}

// round 2
// speedup vs baseline: 2.7722x; 2.7722x over previous
#include <cuda_runtime.h>

#define BB 1024
#define TT 128
#define KK 128
#define START_TAG 126
#define STOP_TAG 127

// order-preserving float<->uint monotone bijection (for __reduce_max_sync)
__device__ __forceinline__ unsigned f2o(float f) {
    unsigned u = __float_as_uint(f);
    return u ^ ((unsigned)((int)u >> 31) | 0x80000000u);
}
__device__ __forceinline__ float o2f(unsigned e) {
    return __uint_as_float(e ^ (~(unsigned)((int)e >> 31) | 0x80000000u));
}

// Per-warp length from the monotone mask row. Mask dtype detected from first word:
// bool -> 0x01010101 (first entries always true, len>=64), float32 -> 0x3F800000, else int32.
__device__ __forceinline__ int warp_len(const void* masks, int b, int lane) {
    unsigned w0 = *(const unsigned*)masks;
    int cnt;
    if (w0 == 0x01010101u) {
        unsigned v = ((const unsigned*)((const char*)masks + (size_t)b * TT))[lane];
        cnt = __popc(v & 0x01010101u);
    } else if (w0 == 0x3F800000u) {
        float4 v = ((const float4*)((const float*)masks + (size_t)b * TT))[lane];
        cnt = (v.x != 0.0f) + (v.y != 0.0f) + (v.z != 0.0f) + (v.w != 0.0f);
    } else {
        int4 v = ((const int4*)((const int*)masks + (size_t)b * TT))[lane];
        cnt = (v.x != 0) + (v.y != 0) + (v.z != 0) + (v.w != 0);
    }
    return __reduce_add_sync(0xffffffffu, cnt);
}

// ---------------------------------------------------------------------------
// Fused Viterbi: warp per batch. Pruned max-plus forward with argmax tracking
// (backpointers in per-warp SMEM), then in-warp STOP argmax + SMEM backtrack.
// SMEM: 64KB transitions + 8 x 16KB backpointers = 192KB -> 1 CTA/SM, 1 wave.
// ---------------------------------------------------------------------------
extern "C" __global__ void __launch_bounds__(256)
viterbi_kernel(const float* __restrict__ feats,
               const float* __restrict__ trans,
               const void*  __restrict__ masks,
               float* __restrict__ out_score,
               float* __restrict__ out_dec) {
    extern __shared__ char smem[];
    float* ts = (float*)smem;                      // [prev*128 + cur], 64 KB
    __shared__ float s_wr[4];
    __shared__ float s_delta;

    int tid = threadIdx.x;

    // Load transitions into smem (coalesced float4)
    for (int i = tid; i < KK * KK / 4; i += 256)
        ((float4*)ts)[i] = ((const float4*)trans)[i];
    __syncthreads();

    // Exact prune bound: Delta = max over cur of (max-min of trans[:,cur]) + FP margin
    if (tid < 128) {
        float mx = -3.4e38f, mn = 3.4e38f;
        #pragma unroll 8
        for (int p = 0; p < 128; p++) {
            float v = ts[p * 128 + tid];
            mx = fmaxf(mx, v); mn = fminf(mn, v);
        }
        float r = mx - mn;
        #pragma unroll
        for (int o = 16; o; o >>= 1) r = fmaxf(r, __shfl_xor_sync(0xffffffffu, r, o));
        if ((tid & 31) == 0) s_wr[tid >> 5] = r;
    }
    __syncthreads();
    if (tid == 0)
        s_delta = fmaxf(fmaxf(s_wr[0], s_wr[1]), fmaxf(s_wr[2], s_wr[3])) + 1e-3f;
    __syncthreads();
    float delta = s_delta;

    int w = tid >> 5, lane = tid & 31;
    int b = blockIdx.x * 8 + w;
    unsigned char* bp = (unsigned char*)(smem + 65536 + w * (TT * KK));  // 16 KB/warp
    int last = warp_len(masks, b, lane) - 1;

    const float* fb = feats + (size_t)b * TT * KK;

    // Strided ownership: lane owns cur/prev = {lane, lane+32, lane+64, lane+96}
    // t = 0: partition = feats[:,0,:] + trans[START,:]
    float v0 = fb[lane]      + ts[START_TAG * KK + lane];
    float v1 = fb[lane + 32] + ts[START_TAG * KK + lane + 32];
    float v2 = fb[lane + 64] + ts[START_TAG * KK + lane + 64];
    float v3 = fb[lane + 96] + ts[START_TAG * KK + lane + 96];

    // prefetch feat row t=1 (len >= 64 so always valid)
    float f0 = fb[KK + lane], f1 = fb[KK + lane + 32];
    float f2 = fb[KK + lane + 64], f3 = fb[KK + lane + 96];

    for (int t = 1; t <= last; t++) {
        float fc0 = f0, fc1 = f1, fc2 = f2, fc3 = f3;
        if (t < last) {
            const float* fn = fb + (t + 1) * KK;
            f0 = fn[lane]; f1 = fn[lane + 32]; f2 = fn[lane + 64]; f3 = fn[lane + 96];
        }

        // warp max of partition via single REDUX on order-preserving uints
        float lm = fmaxf(fmaxf(v0, v1), fmaxf(v2, v3));
        float m = o2f(__reduce_max_sync(0xffffffffu, f2o(lm)));
        float thr = m - delta;

        unsigned c0 = __ballot_sync(0xffffffffu, v0 >= thr);
        unsigned c1 = __ballot_sync(0xffffffffu, v1 >= thr);
        unsigned c2 = __ballot_sync(0xffffffffu, v2 >= thr);
        unsigned c3 = __ballot_sync(0xffffffffu, v3 >= thr);

        // new_part[cur] = max over candidate prev (ascending order -> first-index
        // ties, matching jnp.argmax). q association matches ref: (part+trans)+feat.
        float b0 = -3.4e38f, b1 = -3.4e38f, b2 = -3.4e38f, b3 = -3.4e38f;
        int   i0 = 0, i1 = 0, i2 = 0, i3 = 0;
        #define PROC(MASK, VV, BASE)                                               \
        {   unsigned mm = (MASK);                                                  \
            while (mm) {                                                           \
                int sl = __ffs(mm) - 1; mm &= mm - 1;                              \
                float pv = __shfl_sync(0xffffffffu, (VV), sl);                     \
                int prev = (BASE) + sl;                                            \
                const float* tr = ts + prev * KK + lane;                           \
                float q0 = (pv + tr[0])  + fc0; if (q0 > b0) { b0 = q0; i0 = prev; } \
                float q1 = (pv + tr[32]) + fc1; if (q1 > b1) { b1 = q1; i1 = prev; } \
                float q2 = (pv + tr[64]) + fc2; if (q2 > b2) { b2 = q2; i2 = prev; } \
                float q3 = (pv + tr[96]) + fc3; if (q3 > b3) { b3 = q3; i3 = prev; } \
            }                                                                      \
        }
        PROC(c0, v0, 0)
        PROC(c1, v1, 32)
        PROC(c2, v2, 64)
        PROC(c3, v3, 96)
        #undef PROC

        // packed backpointer store: byte for cur is at (cur&31)*4 + (cur>>5)
        ((unsigned*)(bp + t * KK))[lane] =
            (unsigned)i0 | ((unsigned)i1 << 8) | ((unsigned)i2 << 16) | ((unsigned)i3 << 24);

        v0 = b0; v1 = b1; v2 = b2; v3 = b3;
    }

    // STOP transition argmax from registers (first-index ties)
    float q0 = v0 + ts[lane * KK + STOP_TAG];
    float q1 = v1 + ts[(lane + 32) * KK + STOP_TAG];
    float q2 = v2 + ts[(lane + 64) * KK + STOP_TAG];
    float q3 = v3 + ts[(lane + 96) * KK + STOP_TAG];
    float bv = q0; int bi = lane;
    if (q1 > bv) { bv = q1; bi = lane + 32; }
    if (q2 > bv) { bv = q2; bi = lane + 64; }
    if (q3 > bv) { bv = q3; bi = lane + 96; }
    #pragma unroll
    for (int o = 16; o; o >>= 1) {
        float ov = __shfl_xor_sync(0xffffffffu, bv, o);
        int   oi = __shfl_xor_sync(0xffffffffu, bi, o);
        if (ov > bv || (ov == bv && oi < bi)) { bv = ov; bi = oi; }
    }
    int cur = bi;   // uniform across warp

    if (out_score && lane == 0) out_score[b] = bv;

    if (out_dec) {
        float* od = out_dec + (size_t)b * TT;
        for (int t = last + 1 + lane; t < TT - 1; t += 32) od[t] = 0.0f;  // masked tail
        if (lane == 0) { od[TT - 1] = (float)cur; od[last] = (float)cur; } // ref quirk
        // SMEM pointer chase (all lanes redundant, uniform address -> broadcast)
        for (int t = last; t >= 1; t--) {
            cur = bp[t * KK + ((cur & 31) << 2) + (cur >> 5)];
            if (lane == 0) od[t - 1] = (float)cur;
        }
    }
}

// ---------------------------------------------------------------------------
extern "C" void kernel_launch(void* const* d_in, const int* in_sizes, int n_in,
                              void* d_out, int out_size) {
    const float* feats = nullptr;
    const float* trans = nullptr;
    const void*  masks = nullptr;
    for (int i = 0; i < n_in; i++) {
        if      (in_sizes[i] == BB * TT * KK) feats = (const float*)d_in[i];
        else if (in_sizes[i] == KK * KK)      trans = (const float*)d_in[i];
        else if (in_sizes[i] == BB * TT)      masks = d_in[i];
    }
    if (!feats || !trans || !masks) return;

    float* out   = (float*)d_out;
    float* score = nullptr;
    float* dec   = nullptr;
    if (out_size == BB * TT + BB) { score = out; dec = out + BB; }   // (path_score, decode)
    else if (out_size == BB * TT) { dec = out; }
    else if (out_size == BB)      { score = out; }
    else                          { score = out; if (out_size >= BB * TT + BB) dec = out + BB; }

    int smem_bytes = 65536 + 8 * TT * KK;   // 64KB trans + 128KB backpointers = 196608
    cudaFuncSetAttribute(viterbi_kernel, cudaFuncAttributeMaxDynamicSharedMemorySize, smem_bytes);
    viterbi_kernel<<<BB / 8, 256, smem_bytes>>>(feats, trans, masks, score, dec);
}

// round 3
// speedup vs baseline: 2.8769x; 1.0377x over previous
#include <cuda_runtime.h>

#define BB 1024
#define TT 128
#define KK 128
#define START_TAG 126
#define STOP_TAG 127

// order-preserving float<->uint monotone bijection (for __reduce_max_sync)
__device__ __forceinline__ unsigned f2o(float f) {
    unsigned u = __float_as_uint(f);
    return u ^ ((unsigned)((int)u >> 31) | 0x80000000u);
}
__device__ __forceinline__ float o2f(unsigned e) {
    return __uint_as_float(e ^ (~(unsigned)((int)e >> 31) | 0x80000000u));
}

// Per-warp length from the monotone mask row. Mask dtype detected from first word:
// bool -> 0x01010101, float32 -> 0x3F800000, else int32.
__device__ __forceinline__ int warp_len(const void* masks, int b, int lane) {
    unsigned w0 = *(const unsigned*)masks;
    int cnt;
    if (w0 == 0x01010101u) {
        unsigned v = ((const unsigned*)((const char*)masks + (size_t)b * TT))[lane];
        cnt = __popc(v & 0x01010101u);
    } else if (w0 == 0x3F800000u) {
        float4 v = ((const float4*)((const float*)masks + (size_t)b * TT))[lane];
        cnt = (v.x != 0.0f) + (v.y != 0.0f) + (v.z != 0.0f) + (v.w != 0.0f);
    } else {
        int4 v = ((const int4*)((const int*)masks + (size_t)b * TT))[lane];
        cnt = (v.x != 0) + (v.y != 0) + (v.z != 0) + (v.w != 0);
    }
    return __reduce_add_sync(0xffffffffu, cnt);
}

// ---------------------------------------------------------------------------
// Fused Viterbi: warp per batch, lane owns cur/prev = {4*lane .. 4*lane+3}.
// Pruned max-plus forward with argmax tracking (backpointers in per-warp SMEM),
// feat rows prefetched 4 steps deep in a register ring, then in-warp STOP
// argmax + SMEM backtrack. SMEM: 64KB trans + 8 x 16KB bp = 192KB, 1 CTA/SM.
// ---------------------------------------------------------------------------
extern "C" __global__ void __launch_bounds__(256)
viterbi_kernel(const float* __restrict__ feats,
               const float* __restrict__ trans,
               const void*  __restrict__ masks,
               float* __restrict__ out_score,
               float* __restrict__ out_dec) {
    extern __shared__ char smem[];
    float* ts = (float*)smem;                      // [prev*128 + cur], 64 KB
    __shared__ float s_wr[4];
    __shared__ float s_delta;

    int tid = threadIdx.x;

    for (int i = tid; i < KK * KK / 4; i += 256)
        ((float4*)ts)[i] = ((const float4*)trans)[i];
    __syncthreads();

    // Exact prune bound: Delta = max over cur of (max-min of trans[:,cur]) + margin
    if (tid < 128) {
        float mx = -3.4e38f, mn = 3.4e38f;
        #pragma unroll 8
        for (int p = 0; p < 128; p++) {
            float v = ts[p * 128 + tid];
            mx = fmaxf(mx, v); mn = fminf(mn, v);
        }
        float r = mx - mn;
        #pragma unroll
        for (int o = 16; o; o >>= 1) r = fmaxf(r, __shfl_xor_sync(0xffffffffu, r, o));
        if ((tid & 31) == 0) s_wr[tid >> 5] = r;
    }
    __syncthreads();
    if (tid == 0)
        s_delta = fmaxf(fmaxf(s_wr[0], s_wr[1]), fmaxf(s_wr[2], s_wr[3])) + 1e-3f;
    __syncthreads();
    float delta = s_delta;

    int w = tid >> 5, lane = tid & 31;
    int b = blockIdx.x * 8 + w;
    unsigned char* bp = (unsigned char*)(smem + 65536 + w * (TT * KK));  // 16 KB/warp
    int last = warp_len(masks, b, lane) - 1;       // last >= 63

    const float4* fb4 = (const float4*)(feats + (size_t)b * TT * KK);  // 32 float4 per row

    // t = 0: partition = feats[:,0,:] + trans[START,:]
    float4 f0  = fb4[lane];
    float4 tr0 = ((const float4*)(ts + START_TAG * KK))[lane];
    float v0 = f0.x + tr0.x, v1 = f0.y + tr0.y, v2 = f0.z + tr0.z, v3 = f0.w + tr0.w;

    // feat register ring, depth 4: ring[j] holds row tb+j during block starting at tb
    float4 ring[4];
    #pragma unroll
    for (int j = 0; j < 4; j++) ring[j] = fb4[(1 + j) * 32 + lane];   // rows 1..4 (<= 63 <= last)

    for (int tb = 1; tb <= last; tb += 4) {
        #pragma unroll
        for (int j = 0; j < 4; j++) {
            int t = tb + j;
            if (t > last) break;                   // warp-uniform
            float4 fc = ring[j];
            int tn = t + 4;
            if (tn <= last) ring[j] = fb4[tn * 32 + lane];

            // warp max of partition via single REDUX on order-preserving uints
            float lm = fmaxf(fmaxf(v0, v1), fmaxf(v2, v3));
            float thr = o2f(__reduce_max_sync(0xffffffffu, f2o(lm))) - delta;

            unsigned c0 = __ballot_sync(0xffffffffu, v0 >= thr);
            unsigned c1 = __ballot_sync(0xffffffffu, v1 >= thr);
            unsigned c2 = __ballot_sync(0xffffffffu, v2 >= thr);
            unsigned c3 = __ballot_sync(0xffffffffu, v3 >= thr);

            float b0 = -3.4e38f, b1 = -3.4e38f, b2 = -3.4e38f, b3 = -3.4e38f;
            int   i0 = 0, i1 = 0, i2 = 0, i3 = 0;
            // q association matches ref: (part + trans) + feat
            #define PROC(MASK, VV, COMP)                                                 \
            {   unsigned mm = (MASK);                                                    \
                while (mm) {                                                             \
                    int sl = __ffs(mm) - 1; mm &= mm - 1;                                \
                    float pv = __shfl_sync(0xffffffffu, (VV), sl);                       \
                    int prev = sl * 4 + (COMP);                                          \
                    float4 tr = ((const float4*)(ts + prev * KK))[lane];                 \
                    float q0 = (pv + tr.x) + fc.x; if (q0 > b0) { b0 = q0; i0 = prev; }  \
                    float q1 = (pv + tr.y) + fc.y; if (q1 > b1) { b1 = q1; i1 = prev; }  \
                    float q2 = (pv + tr.z) + fc.z; if (q2 > b2) { b2 = q2; i2 = prev; }  \
                    float q3 = (pv + tr.w) + fc.w; if (q3 > b3) { b3 = q3; i3 = prev; }  \
                }                                                                        \
            }
            PROC(c0, v0, 0)
            PROC(c1, v1, 1)
            PROC(c2, v2, 2)
            PROC(c3, v3, 3)
            #undef PROC

            // packed backpointers: byte for cur=c at bp[t*128 + c]
            ((unsigned*)(bp + t * KK))[lane] =
                (unsigned)i0 | ((unsigned)i1 << 8) | ((unsigned)i2 << 16) | ((unsigned)i3 << 24);

            v0 = b0; v1 = b1; v2 = b2; v3 = b3;
        }
    }

    // STOP transition argmax (first-index ties)
    int s0 = lane * 4;
    float q0 = v0 + ts[(s0 + 0) * KK + STOP_TAG];
    float q1 = v1 + ts[(s0 + 1) * KK + STOP_TAG];
    float q2 = v2 + ts[(s0 + 2) * KK + STOP_TAG];
    float q3 = v3 + ts[(s0 + 3) * KK + STOP_TAG];
    float bv = q0; int bi = s0;
    if (q1 > bv) { bv = q1; bi = s0 + 1; }
    if (q2 > bv) { bv = q2; bi = s0 + 2; }
    if (q3 > bv) { bv = q3; bi = s0 + 3; }
    #pragma unroll
    for (int o = 16; o; o >>= 1) {
        float ov = __shfl_xor_sync(0xffffffffu, bv, o);
        int   oi = __shfl_xor_sync(0xffffffffu, bi, o);
        if (ov > bv || (ov == bv && oi < bi)) { bv = ov; bi = oi; }
    }
    int cur = bi;   // warp-uniform

    if (out_score && lane == 0) out_score[b] = bv;

    if (out_dec) {
        float* od = out_dec + (size_t)b * TT;
        for (int t = last + 1 + lane; t < TT - 1; t += 32) od[t] = 0.0f;   // masked tail
        if (lane == 0) { od[TT - 1] = (float)cur; od[last] = (float)cur; } // ref quirk
        for (int t = last; t >= 1; t--) {
            cur = bp[t * KK + cur];                 // uniform SMEM pointer chase
            if (lane == 0) od[t - 1] = (float)cur;
        }
    }
}

// ---------------------------------------------------------------------------
extern "C" void kernel_launch(void* const* d_in, const int* in_sizes, int n_in,
                              void* d_out, int out_size) {
    const float* feats = nullptr;
    const float* trans = nullptr;
    const void*  masks = nullptr;
    for (int i = 0; i < n_in; i++) {
        if      (in_sizes[i] == BB * TT * KK) feats = (const float*)d_in[i];
        else if (in_sizes[i] == KK * KK)      trans = (const float*)d_in[i];
        else if (in_sizes[i] == BB * TT)      masks = d_in[i];
    }
    if (!feats || !trans || !masks) return;

    float* out   = (float*)d_out;
    float* score = nullptr;
    float* dec   = nullptr;
    if (out_size == BB * TT + BB) { score = out; dec = out + BB; }   // (path_score, decode)
    else if (out_size == BB * TT) { dec = out; }
    else if (out_size == BB)      { score = out; }
    else                          { score = out; if (out_size >= BB * TT + BB) dec = out + BB; }

    int smem_bytes = 65536 + 8 * TT * KK;   // 64KB trans + 128KB backpointers
    cudaFuncSetAttribute(viterbi_kernel, cudaFuncAttributeMaxDynamicSharedMemorySize, smem_bytes);
    viterbi_kernel<<<BB / 8, 256, smem_bytes>>>(feats, trans, masks, score, dec);
}

// round 4
// speedup vs baseline: 3.3899x; 1.1783x over previous
#include <cuda_runtime.h>

#define BB 1024
#define TT 128
#define KK 128
#define START_TAG 126
#define STOP_TAG 127

// order-preserving float<->uint monotone bijection (for __reduce_max_sync)
__device__ __forceinline__ unsigned f2o(float f) {
    unsigned u = __float_as_uint(f);
    return u ^ ((unsigned)((int)u >> 31) | 0x80000000u);
}
__device__ __forceinline__ float o2f(unsigned e) {
    return __uint_as_float(e ^ (~(unsigned)((int)e >> 31) | 0x80000000u));
}

// Per-warp length from the monotone mask row. Mask dtype detected from first word:
// bool -> 0x01010101, float32 -> 0x3F800000, else int32.
__device__ __forceinline__ int warp_len(const void* masks, int b, int lane) {
    unsigned w0 = *(const unsigned*)masks;
    int cnt;
    if (w0 == 0x01010101u) {
        unsigned v = ((const unsigned*)((const char*)masks + (size_t)b * TT))[lane];
        cnt = __popc(v & 0x01010101u);
    } else if (w0 == 0x3F800000u) {
        float4 v = ((const float4*)((const float*)masks + (size_t)b * TT))[lane];
        cnt = (v.x != 0.0f) + (v.y != 0.0f) + (v.z != 0.0f) + (v.w != 0.0f);
    } else {
        int4 v = ((const int4*)((const int*)masks + (size_t)b * TT))[lane];
        cnt = (v.x != 0) + (v.y != 0) + (v.z != 0) + (v.w != 0);
    }
    return __reduce_add_sync(0xffffffffu, cnt);
}

// ---------------------------------------------------------------------------
// Fused Viterbi: warp per batch, lane owns cur/prev = {4*lane .. 4*lane+3}.
// Pruned max-plus forward: candidates compacted into per-warp SMEM records,
// processed in a fixed-trip unrolled loop (pipelined LDS, no shfl on hot path).
// Backpointers in per-warp SMEM; in-warp STOP argmax + SMEM backtrack.
// SMEM: 64KB trans + 8x16KB bp + 8x2KB cand = 208KB -> 1 CTA/SM, 1 wave.
// ---------------------------------------------------------------------------
extern "C" __global__ void __launch_bounds__(256)
viterbi_kernel(const float* __restrict__ feats,
               const float* __restrict__ trans,
               const void*  __restrict__ masks,
               float* __restrict__ out_score,
               float* __restrict__ out_dec) {
    extern __shared__ char smem[];
    float* ts = (float*)smem;                      // [prev*128 + cur], 64 KB
    __shared__ float s_wr[4];
    __shared__ float s_delta;

    int tid = threadIdx.x;

    for (int i = tid; i < KK * KK / 4; i += 256)
        ((float4*)ts)[i] = ((const float4*)trans)[i];
    __syncthreads();

    // Exact prune bound: Delta = max over cur of (max-min of trans[:,cur]) + margin
    if (tid < 128) {
        float mx = -3.4e38f, mn = 3.4e38f;
        #pragma unroll 8
        for (int p = 0; p < 128; p++) {
            float v = ts[p * 128 + tid];
            mx = fmaxf(mx, v); mn = fminf(mn, v);
        }
        float r = mx - mn;
        #pragma unroll
        for (int o = 16; o; o >>= 1) r = fmaxf(r, __shfl_xor_sync(0xffffffffu, r, o));
        if ((tid & 31) == 0) s_wr[tid >> 5] = r;
    }
    __syncthreads();
    if (tid == 0)
        s_delta = fmaxf(fmaxf(s_wr[0], s_wr[1]), fmaxf(s_wr[2], s_wr[3])) + 1e-3f;
    __syncthreads();
    float delta = s_delta;

    int w = tid >> 5, lane = tid & 31;
    int b = blockIdx.x * 8 + w;
    unsigned char* bp = (unsigned char*)(smem + 65536 + w * (TT * KK));     // 16 KB/warp
    uint2* cand = (uint2*)(smem + 65536 + 8 * TT * KK + w * 2048);          // 2 x 128 rec/warp
    const float4* ts4 = (const float4*)ts;
    int last = warp_len(masks, b, lane) - 1;       // last >= 63

    const float4* fb4 = (const float4*)(feats + (size_t)b * TT * KK);  // 32 float4/row

    // t = 0: partition = feats[:,0,:] + trans[START,:]
    float4 f0  = fb4[lane];
    float4 tr0 = ((const float4*)(ts + START_TAG * KK))[lane];
    float v0 = f0.x + tr0.x, v1 = f0.y + tr0.y, v2 = f0.z + tr0.z, v3 = f0.w + tr0.w;

    // feat register ring, depth 4
    float4 ring[4];
    #pragma unroll
    for (int j = 0; j < 4; j++) ring[j] = fb4[(1 + j) * 32 + lane];   // rows 1..4

    unsigned lmask = (1u << lane) - 1u;
    int p0 = lane * 4;

    for (int tb = 1; tb <= last; tb += 4) {
        #pragma unroll
        for (int j = 0; j < 4; j++) {
            int t = tb + j;
            if (t > last) break;                   // warp-uniform
            float4 fc = ring[j];
            int tn = t + 4;
            if (tn <= last) ring[j] = fb4[tn * 32 + lane];

            // threshold from warp max (single REDUX on order-preserving uints)
            float lm = fmaxf(fmaxf(v0, v1), fmaxf(v2, v3));
            float thr = o2f(__reduce_max_sync(0xffffffffu, f2o(lm))) - delta;

            unsigned c0 = __ballot_sync(0xffffffffu, v0 >= thr);
            unsigned c1 = __ballot_sync(0xffffffffu, v1 >= thr);
            unsigned c2 = __ballot_sync(0xffffffffu, v2 >= thr);
            unsigned c3 = __ballot_sync(0xffffffffu, v3 >= thr);
            int n0 = __popc(c0), n01 = n0 + __popc(c1), n012 = n01 + __popc(c2);
            int ncand = n012 + __popc(c3);

            // compact candidates (pv, prev) into double-buffered SMEM staging;
            // comp-major order (prev = 0,4,..,124, 1,5,.., ...) = prior rounds' order
            uint2* cb = cand + ((t & 1) << 7);
            if ((c0 >> lane) & 1u) cb[       __popc(c0 & lmask)] = make_uint2(__float_as_uint(v0), p0 + 0);
            if ((c1 >> lane) & 1u) cb[n0   + __popc(c1 & lmask)] = make_uint2(__float_as_uint(v1), p0 + 1);
            if ((c2 >> lane) & 1u) cb[n01  + __popc(c2 & lmask)] = make_uint2(__float_as_uint(v2), p0 + 2);
            if ((c3 >> lane) & 1u) cb[n012 + __popc(c3 & lmask)] = make_uint2(__float_as_uint(v3), p0 + 3);
            __syncwarp();

            // fixed-trip pipelined candidate loop; q matches ref: (part+trans)+feat
            float b0 = -3.4e38f, b1 = -3.4e38f, b2 = -3.4e38f, b3 = -3.4e38f;
            int   i0 = 0, i1 = 0, i2 = 0, i3 = 0;
            #pragma unroll 4
            for (int k = 0; k < ncand; k++) {
                uint2 r = cb[k];
                float pv = __uint_as_float(r.x);
                int prev = (int)r.y;
                float4 tr = ts4[prev * 32 + lane];
                float q0 = (pv + tr.x) + fc.x; if (q0 > b0) { b0 = q0; i0 = prev; }
                float q1 = (pv + tr.y) + fc.y; if (q1 > b1) { b1 = q1; i1 = prev; }
                float q2 = (pv + tr.z) + fc.z; if (q2 > b2) { b2 = q2; i2 = prev; }
                float q3 = (pv + tr.w) + fc.w; if (q3 > b3) { b3 = q3; i3 = prev; }
            }

            // packed backpointers: byte for cur=c at bp[t*128 + c]
            ((unsigned*)(bp + t * KK))[lane] =
                (unsigned)i0 | ((unsigned)i1 << 8) | ((unsigned)i2 << 16) | ((unsigned)i3 << 24);

            v0 = b0; v1 = b1; v2 = b2; v3 = b3;
        }
    }

    // STOP transition argmax (first-index ties)
    float q0 = v0 + ts[(p0 + 0) * KK + STOP_TAG];
    float q1 = v1 + ts[(p0 + 1) * KK + STOP_TAG];
    float q2 = v2 + ts[(p0 + 2) * KK + STOP_TAG];
    float q3 = v3 + ts[(p0 + 3) * KK + STOP_TAG];
    float bv = q0; int bi = p0;
    if (q1 > bv) { bv = q1; bi = p0 + 1; }
    if (q2 > bv) { bv = q2; bi = p0 + 2; }
    if (q3 > bv) { bv = q3; bi = p0 + 3; }
    #pragma unroll
    for (int o = 16; o; o >>= 1) {
        float ov = __shfl_xor_sync(0xffffffffu, bv, o);
        int   oi = __shfl_xor_sync(0xffffffffu, bi, o);
        if (ov > bv || (ov == bv && oi < bi)) { bv = ov; bi = oi; }
    }
    int cur = bi;   // warp-uniform

    if (out_score && lane == 0) out_score[b] = bv;

    if (out_dec) {
        float* od = out_dec + (size_t)b * TT;
        for (int t = last + 1 + lane; t < TT - 1; t += 32) od[t] = 0.0f;   // masked tail
        if (lane == 0) { od[TT - 1] = (float)cur; od[last] = (float)cur; } // ref quirk
        for (int t = last; t >= 1; t--) {
            cur = bp[t * KK + cur];                 // uniform SMEM pointer chase
            if (lane == 0) od[t - 1] = (float)cur;
        }
    }
}

// ---------------------------------------------------------------------------
extern "C" void kernel_launch(void* const* d_in, const int* in_sizes, int n_in,
                              void* d_out, int out_size) {
    const float* feats = nullptr;
    const float* trans = nullptr;
    const void*  masks = nullptr;
    for (int i = 0; i < n_in; i++) {
        if      (in_sizes[i] == BB * TT * KK) feats = (const float*)d_in[i];
        else if (in_sizes[i] == KK * KK)      trans = (const float*)d_in[i];
        else if (in_sizes[i] == BB * TT)      masks = d_in[i];
    }
    if (!feats || !trans || !masks) return;

    float* out   = (float*)d_out;
    float* score = nullptr;
    float* dec   = nullptr;
    if (out_size == BB * TT + BB) { score = out; dec = out + BB; }   // (path_score, decode)
    else if (out_size == BB * TT) { dec = out; }
    else if (out_size == BB)      { score = out; }
    else                          { score = out; if (out_size >= BB * TT + BB) dec = out + BB; }

    int smem_bytes = 65536 + 8 * TT * KK + 8 * 2048;   // trans + bp + cand staging = 212992
    cudaFuncSetAttribute(viterbi_kernel, cudaFuncAttributeMaxDynamicSharedMemorySize, smem_bytes);
    viterbi_kernel<<<BB / 8, 256, smem_bytes>>>(feats, trans, masks, score, dec);
}

// round 6
// speedup vs baseline: 3.5712x; 1.0535x over previous
#include <cuda_runtime.h>

#define BB 1024
#define TT 128
#define KK 128
#define START_TAG 126
#define STOP_TAG 127

// order-preserving float<->uint monotone bijection (for __reduce_max_sync)
__device__ __forceinline__ unsigned f2o(float f) {
    unsigned u = __float_as_uint(f);
    return u ^ ((unsigned)((int)u >> 31) | 0x80000000u);
}
__device__ __forceinline__ float o2f(unsigned e) {
    return __uint_as_float(e ^ (~(unsigned)((int)e >> 31) | 0x80000000u));
}

// Per-warp length from the monotone mask row. Mask dtype detected from first word.
__device__ __forceinline__ int warp_len(const void* masks, int b, int lane) {
    unsigned w0 = *(const unsigned*)masks;
    int cnt;
    if (w0 == 0x01010101u) {
        unsigned v = ((const unsigned*)((const char*)masks + (size_t)b * TT))[lane];
        cnt = __popc(v & 0x01010101u);
    } else if (w0 == 0x3F800000u) {
        float4 v = ((const float4*)((const float*)masks + (size_t)b * TT))[lane];
        cnt = (v.x != 0.0f) + (v.y != 0.0f) + (v.z != 0.0f) + (v.w != 0.0f);
    } else {
        int4 v = ((const int4*)((const int*)masks + (size_t)b * TT))[lane];
        cnt = (v.x != 0) + (v.y != 0) + (v.z != 0) + (v.w != 0);
    }
    return __reduce_add_sync(0xffffffffu, cnt);
}

// ---------------------------------------------------------------------------
// Fused Viterbi: warp per batch, lane owns cur/prev = {4*lane .. 4*lane+3}.
// STRAIGHT-LINE forward: every warp runs exactly 127 steps (no per-step
// branches); partition snapshotted at t==last via predicated selects.
// Candidates compacted to SMEM records padded with -FLT_MAX dummies and
// processed in fixed groups of 4 (2x LDS.128). Backpointers in per-warp SMEM.
// SMEM: 64KB trans + 8x16KB bp + 8x2112B staging = ~208KB -> 1 CTA/SM.
// ---------------------------------------------------------------------------
extern "C" __global__ void __launch_bounds__(256, 1)
viterbi_kernel(const float* __restrict__ feats,
               const float* __restrict__ trans,
               const void*  __restrict__ masks,
               float* __restrict__ out_score,
               float* __restrict__ out_dec) {
    extern __shared__ char smem[];
    float* ts = (float*)smem;                      // [prev*128 + cur], 64 KB
    __shared__ float s_wr[4];
    __shared__ float s_delta;

    int tid = threadIdx.x;

    for (int i = tid; i < KK * KK / 4; i += 256)
        ((float4*)ts)[i] = ((const float4*)trans)[i];
    __syncthreads();

    // Exact prune bound: Delta = max over cur of (max-min of trans[:,cur]) + margin
    if (tid < 128) {
        float mx = -3.4e38f, mn = 3.4e38f;
        #pragma unroll 8
        for (int p = 0; p < 128; p++) {
            float v = ts[p * 128 + tid];
            mx = fmaxf(mx, v); mn = fminf(mn, v);
        }
        float r = mx - mn;
        #pragma unroll
        for (int o = 16; o; o >>= 1) r = fmaxf(r, __shfl_xor_sync(0xffffffffu, r, o));
        if ((tid & 31) == 0) s_wr[tid >> 5] = r;
    }
    __syncthreads();
    if (tid == 0)
        s_delta = fmaxf(fmaxf(s_wr[0], s_wr[1]), fmaxf(s_wr[2], s_wr[3])) + 1e-3f;
    __syncthreads();
    float delta = s_delta;

    int w = tid >> 5, lane = tid & 31;
    int b = blockIdx.x * 8 + w;
    unsigned char* bp = (unsigned char*)(smem + 65536 + w * (TT * KK));       // 16 KB/warp
    uint2* cand = (uint2*)(smem + 65536 + 8 * TT * KK + w * 2112);            // 2 x 132 recs
    const float4* ts4 = (const float4*)ts;
    int last = warp_len(masks, b, lane) - 1;       // last >= 63

    const float4* fb4 = (const float4*)(feats + (size_t)b * TT * KK);  // 32 float4/row

    // t = 0: partition = feats[:,0,:] + trans[START,:]
    float4 f0  = fb4[lane];
    float4 tr0 = ((const float4*)(ts + START_TAG * KK))[lane];
    float v0 = f0.x + tr0.x, v1 = f0.y + tr0.y, v2 = f0.z + tr0.z, v3 = f0.w + tr0.w;
    float sv0 = v0, sv1 = v1, sv2 = v2, sv3 = v3;  // snapshot at t == last

    unsigned lmask = (1u << lane) - 1u;
    int p0 = lane * 4;

    // one Viterbi step (straight-line; no data-dependent control flow)
    auto step = [&](int t, float4 fc) {
        // threshold from warp max (single REDUX on order-preserving uints)
        float lm = fmaxf(fmaxf(v0, v1), fmaxf(v2, v3));
        float thr = o2f(__reduce_max_sync(0xffffffffu, f2o(lm))) - delta;

        unsigned c0 = __ballot_sync(0xffffffffu, v0 >= thr);
        unsigned c1 = __ballot_sync(0xffffffffu, v1 >= thr);
        unsigned c2 = __ballot_sync(0xffffffffu, v2 >= thr);
        unsigned c3 = __ballot_sync(0xffffffffu, v3 >= thr);
        int n0 = __popc(c0), n01 = n0 + __popc(c1), n012 = n01 + __popc(c2);
        int ncand = n012 + __popc(c3);

        // compact candidates (pv, prev) into double-buffered SMEM staging
        // (comp-major order: prev = 0,4,..,124, then 1,5,.., ...)
        uint2* cb = cand + ((t & 1) ? 132 : 0);
        if ((c0 >> lane) & 1u) cb[       __popc(c0 & lmask)] = make_uint2(__float_as_uint(v0), p0 + 0);
        if ((c1 >> lane) & 1u) cb[n0   + __popc(c1 & lmask)] = make_uint2(__float_as_uint(v1), p0 + 1);
        if ((c2 >> lane) & 1u) cb[n01  + __popc(c2 & lmask)] = make_uint2(__float_as_uint(v2), p0 + 2);
        if ((c3 >> lane) & 1u) cb[n012 + __popc(c3 & lmask)] = make_uint2(__float_as_uint(v3), p0 + 3);
        if (lane < 3)          cb[ncand + lane] = make_uint2(0xFF7FFFFFu, 0);   // -FLT_MAX pad
        __syncwarp();

        // fixed-shape candidate loop: groups of 4 records (2x LDS.128)
        float b0 = -3.4e38f, b1 = -3.4e38f, b2 = -3.4e38f, b3 = -3.4e38f;
        int   i0 = 0, i1 = 0, i2 = 0, i3 = 0;
        int ng = (ncand + 3) >> 2;
        const uint4* cb4 = (const uint4*)cb;
        #pragma unroll 2
        for (int g = 0; g < ng; g++) {
            uint4 ra = cb4[2 * g];
            uint4 rb = cb4[2 * g + 1];
            #define PROC(PVU, PREV)                                                      \
            {   float pv = __uint_as_float(PVU); int prev = (int)(PREV);                 \
                float4 tr = ts4[prev * 32 + lane];                                       \
                float q0 = (pv + tr.x) + fc.x; if (q0 > b0) { b0 = q0; i0 = prev; }      \
                float q1 = (pv + tr.y) + fc.y; if (q1 > b1) { b1 = q1; i1 = prev; }      \
                float q2 = (pv + tr.z) + fc.z; if (q2 > b2) { b2 = q2; i2 = prev; }      \
                float q3 = (pv + tr.w) + fc.w; if (q3 > b3) { b3 = q3; i3 = prev; }      \
            }
            PROC(ra.x, ra.y) PROC(ra.z, ra.w) PROC(rb.x, rb.y) PROC(rb.z, rb.w)
            #undef PROC
        }

        // packed backpointers: byte for cur=c at bp[t*128 + c]
        ((unsigned*)(bp + t * KK))[lane] =
            (unsigned)i0 | ((unsigned)i1 << 8) | ((unsigned)i2 << 16) | ((unsigned)i3 << 24);

        v0 = b0; v1 = b1; v2 = b2; v3 = b3;
        bool atlast = (t == last);                 // predicated snapshot (off-chain)
        sv0 = atlast ? v0 : sv0; sv1 = atlast ? v1 : sv1;
        sv2 = atlast ? v2 : sv2; sv3 = atlast ? v3 : sv3;
    };

    // feat register ring, depth 4; refill clamped to row 127 (dup row, never consumed)
    float4 r0 = fb4[1 * 32 + lane], r1 = fb4[2 * 32 + lane];
    float4 r2 = fb4[3 * 32 + lane], r3 = fb4[4 * 32 + lane];

    #pragma unroll 1
    for (int tb = 1; tb <= 121; tb += 4) {
        int a4 = min(tb + 4, 127) * 32 + lane, a5 = min(tb + 5, 127) * 32 + lane;
        int a6 = min(tb + 6, 127) * 32 + lane, a7 = min(tb + 7, 127) * 32 + lane;
        float4 fa = r0;  r0 = fb4[a4]; step(tb + 0, fa);
        float4 fb_ = r1; r1 = fb4[a5]; step(tb + 1, fb_);
        float4 fcx = r2; r2 = fb4[a6]; step(tb + 2, fcx);
        float4 fd = r3;  r3 = fb4[a7]; step(tb + 3, fd);
    }
    step(125, r0); step(126, r1); step(127, r2);   // peeled tail (t = 1..127 total)

    // STOP transition argmax from snapshot (first-index ties)
    float q0 = sv0 + ts[(p0 + 0) * KK + STOP_TAG];
    float q1 = sv1 + ts[(p0 + 1) * KK + STOP_TAG];
    float q2 = sv2 + ts[(p0 + 2) * KK + STOP_TAG];
    float q3 = sv3 + ts[(p0 + 3) * KK + STOP_TAG];
    float bv = q0; int bi = p0;
    if (q1 > bv) { bv = q1; bi = p0 + 1; }
    if (q2 > bv) { bv = q2; bi = p0 + 2; }
    if (q3 > bv) { bv = q3; bi = p0 + 3; }
    #pragma unroll
    for (int o = 16; o; o >>= 1) {
        float ov = __shfl_xor_sync(0xffffffffu, bv, o);
        int   oi = __shfl_xor_sync(0xffffffffu, bi, o);
        if (ov > bv || (ov == bv && oi < bi)) { bv = ov; bi = oi; }
    }
    int cur = bi;   // warp-uniform

    if (out_score && lane == 0) out_score[b] = bv;

    if (out_dec) {
        float* od = out_dec + (size_t)b * TT;
        for (int t = last + 1 + lane; t < TT - 1; t += 32) od[t] = 0.0f;   // masked tail
        if (lane == 0) { od[TT - 1] = (float)cur; od[last] = (float)cur; } // ref quirk
        for (int t = last; t >= 1; t--) {
            cur = bp[t * KK + cur];                 // uniform SMEM pointer chase
            if (lane == 0) od[t - 1] = (float)cur;
        }
    }
}

// ---------------------------------------------------------------------------
extern "C" void kernel_launch(void* const* d_in, const int* in_sizes, int n_in,
                              void* d_out, int out_size) {
    const float* feats = nullptr;
    const float* trans = nullptr;
    const void*  masks = nullptr;
    for (int i = 0; i < n_in; i++) {
        if      (in_sizes[i] == BB * TT * KK) feats = (const float*)d_in[i];
        else if (in_sizes[i] == KK * KK)      trans = (const float*)d_in[i];
        else if (in_sizes[i] == BB * TT)      masks = d_in[i];
    }
    if (!feats || !trans || !masks) return;

    float* out   = (float*)d_out;
    float* score = nullptr;
    float* dec   = nullptr;
    if (out_size == BB * TT + BB) { score = out; dec = out + BB; }   // (path_score, decode)
    else if (out_size == BB * TT) { dec = out; }
    else if (out_size == BB)      { score = out; }
    else                          { score = out; if (out_size >= BB * TT + BB) dec = out + BB; }

    int smem_bytes = 65536 + 8 * TT * KK + 8 * 2112;   // trans + bp + staging = 213504
    cudaFuncSetAttribute(viterbi_kernel, cudaFuncAttributeMaxDynamicSharedMemorySize, smem_bytes);
    viterbi_kernel<<<BB / 8, 256, smem_bytes>>>(feats, trans, masks, score, dec);
}